// round 5
// baseline (speedup 1.0000x reference)
#include <cuda_runtime.h>

#define MM 4096
#define NN 4096
#define PLANE (MM * NN)
#define MAX_IT 20
#define F_SIGMA 14.285714285714285f   // 1/(7*0.01)
#define F_TAU 0.01f
#define F_LT 0.07f                    // LAMBDA_ROF * TAU
#define F_THETA 0.5f
#define F_INV_DENOM (1.0f / 1.07f)

#define TS 32          // output tile
#define ES 36          // tile + 2*halo(2)
#define BX 32
#define BY 8
#define NTHREADS (BX * BY)

// Ping-pong scratch (allocation-free rule: __device__ globals)
__device__ float g_x[2][PLANE];
__device__ float g_xt[2][PLANE];
__device__ float g_y[2][2 * PLANE];

__device__ __forceinline__ float clip1(float v) {
    return fminf(fmaxf(v, -1.0f), 1.0f);
}

// Two fused primal-dual iterations per kernel, smem-tiled with halo 2.
// 256 threads (32x8), each handling 4-5 stencil points per phase, so that
// smem (36.3KB) — not threads — bounds occupancy: 6 CTAs/SM for latency hiding.
__global__ __launch_bounds__(NTHREADS) void pd_iter2(
    int first, int last, int in_b, int out_b,
    const float* __restrict__ img,
    const float* __restrict__ w,
    const float* __restrict__ y0p,
    float* __restrict__ dout)
{
    __shared__ float s_xt[ES * ES];
    __shared__ float s_x [ES * ES];
    __shared__ float s_y0[ES * ES];
    __shared__ float s_y1[ES * ES];
    __shared__ float s_w0[ES * ES];
    __shared__ float s_w1[ES * ES];
    __shared__ float s_im[ES * ES];

    const int tx = threadIdx.x;
    const int ty = threadIdx.y;
    const int gi0 = blockIdx.y * TS;
    const int gj0 = blockIdx.x * TS;

    const float* __restrict__ xt_in = first ? img : g_xt[in_b];
    const float* __restrict__ x_in  = first ? img : g_x[in_b];
    const float* __restrict__ y0_in = first ? y0p : g_y[in_b];
    const float* __restrict__ y1_in = first ? (y0p + PLANE) : (g_y[in_b] + PLANE);
    const float* __restrict__ w0 = w;
    const float* __restrict__ w1 = w + PLANE;
    float* __restrict__ x_out  = g_x[out_b];
    float* __restrict__ xt_out = last ? dout : g_xt[out_b];
    float* __restrict__ y_out  = g_y[out_b];

    // ---- load: xt on rows/cols [0,36); y,w on [0,35); x,img on [1,35)
    //      (local index c = r*ES + q, logical li = r-2, lj = q-2)
    #pragma unroll
    for (int r = ty; r < ES; r += BY) {
        const int gi = gi0 + r - 2;
        #pragma unroll
        for (int q = tx; q < ES; q += BX) {
            const int gj = gj0 + q - 2;
            const bool in = ((unsigned)gi < MM) && ((unsigned)gj < NN);
            const int g = gi * NN + gj;
            const int c = r * ES + q;
            s_xt[c] = in ? xt_in[g] : 0.0f;
            if (r < 35 && q < 35) {
                s_y0[c] = in ? y0_in[g] : 0.0f;
                s_y1[c] = in ? y1_in[g] : 0.0f;
                s_w0[c] = in ? w0[g] : 0.0f;
                s_w1[c] = in ? w1[g] : 0.0f;
                if (r >= 1 && q >= 1) {
                    s_x[c]  = in ? x_in[g] : 0.0f;
                    s_im[c] = in ? img[g]  : 0.0f;
                }
            }
        }
    }
    __syncthreads();

    // ---- phase 1a: dual (iter 1), y' on 35x35 in-place
    #pragma unroll
    for (int r = ty; r < 35; r += BY) {
        const int gi = gi0 + r - 2;
        #pragma unroll
        for (int q = tx; q < 35; q += BX) {
            const int gj = gj0 + q - 2;
            const int c = r * ES + q;
            const float xtc = s_xt[c];
            const float gx = (gj < NN - 1) ? (s_xt[c + 1]  - xtc) : 0.0f;
            const float gy = (gi < MM - 1) ? (s_xt[c + ES] - xtc) : 0.0f;
            s_y0[c] = clip1(s_y0[c] + F_SIGMA * s_w0[c] * gx);
            s_y1[c] = clip1(s_y1[c] + F_SIGMA * s_w1[c] * gy);
        }
    }
    __syncthreads();

    // ---- phase 1b: primal + relax (iter 1), x'/xt' on 34x34 in-place
    #pragma unroll
    for (int r = ty + 1; r < 35; r += BY) {
        const int gi = gi0 + r - 2;
        #pragma unroll
        for (int q = tx + 1; q < 35; q += BX) {
            const int gj = gj0 + q - 2;
            const int c = r * ES + q;
            const float h_c = s_w0[c] * s_y0[c];
            const float v_c = s_w1[c] * s_y1[c];
            float dh;
            if (gj == 0) dh = h_c;
            else {
                const float h_l = s_w0[c - 1] * s_y0[c - 1];
                dh = (gj == NN - 1) ? -h_l : (h_c - h_l);
            }
            float dv;
            if (gi == 0) dv = v_c;
            else {
                const float v_u = s_w1[c - ES] * s_y1[c - ES];
                dv = (gi == MM - 1) ? -v_u : (v_c - v_u);
            }
            const float xo = s_x[c];
            const float xn = (xo + F_TAU * (dh + dv) + F_LT * s_im[c]) * F_INV_DENOM;
            s_x[c]  = xn;
            s_xt[c] = xn + F_THETA * (xn - xo);   // raw xt dead after 1a
        }
    }
    __syncthreads();

    // ---- phase 2a: dual (iter 2), y'' on 33x33 in-place; tile part to gmem
    #pragma unroll
    for (int r = ty + 1; r < 34; r += BY) {
        const int gi = gi0 + r - 2;
        #pragma unroll
        for (int q = tx + 1; q < 34; q += BX) {
            const int gj = gj0 + q - 2;
            const int c = r * ES + q;
            const float xtc = s_xt[c];
            const float gx = (gj < NN - 1) ? (s_xt[c + 1]  - xtc) : 0.0f;
            const float gy = (gi < MM - 1) ? (s_xt[c + ES] - xtc) : 0.0f;
            const float y0n = clip1(s_y0[c] + F_SIGMA * s_w0[c] * gx);
            const float y1n = clip1(s_y1[c] + F_SIGMA * s_w1[c] * gy);
            s_y0[c] = y0n;
            s_y1[c] = y1n;
            if (r >= 2 && q >= 2) {
                const int g = gi * NN + gj;
                y_out[g]         = y0n;
                y_out[g + PLANE] = y1n;
            }
        }
    }
    __syncthreads();

    // ---- phase 2b: primal + relax (iter 2) on the 32x32 tile
    #pragma unroll
    for (int r = ty + 2; r < 34; r += BY) {
        const int gi = gi0 + r - 2;
        const int gj = gj0 + tx;
        const int c = r * ES + (tx + 2);
        const float h_c = s_w0[c] * s_y0[c];
        const float v_c = s_w1[c] * s_y1[c];
        float dh;
        if (gj == 0) dh = h_c;
        else {
            const float h_l = s_w0[c - 1] * s_y0[c - 1];
            dh = (gj == NN - 1) ? -h_l : (h_c - h_l);
        }
        float dv;
        if (gi == 0) dv = v_c;
        else {
            const float v_u = s_w1[c - ES] * s_y1[c - ES];
            dv = (gi == MM - 1) ? -v_u : (v_c - v_u);
        }
        const float xo = s_x[c];
        const float xn = (xo + F_TAU * (dh + dv) + F_LT * s_im[c]) * F_INV_DENOM;
        const int g = gi * NN + gj;
        x_out[g]  = xn;
        xt_out[g] = xn + F_THETA * (xn - xo);
    }
}

extern "C" void kernel_launch(void* const* d_in, const int* in_sizes, int n_in,
                              void* d_out, int out_size) {
    const float* img = (const float*)d_in[0];   // [1, 4096, 4096]
    const float* w   = (const float*)d_in[1];   // [2, 4096, 4096]
    const float* y0  = (const float*)d_in[2];   // [2, 4096, 4096]
    float* out = (float*)d_out;

    dim3 block(BX, BY);
    dim3 grid(NN / TS, MM / TS);

    for (int k = 0; k < MAX_IT / 2; ++k) {
        const int first = (k == 0);
        const int last  = (k == MAX_IT / 2 - 1);
        const int in_b  = k & 1;
        const int out_b = (k + 1) & 1;
        pd_iter2<<<grid, block>>>(first, last, in_b, out_b, img, w, y0, out);
    }
}

// round 8
// speedup vs baseline: 1.7870x; 1.7870x over previous
#include <cuda_runtime.h>
#include <cuda_fp16.h>

#define MM 4096
#define NN 4096
#define PLANE (MM * NN)
#define MAX_IT 20
#define F_SIGMA 14.285714285714285f   // 1/(7*0.01)
#define F_TAU 0.01f
#define F_LT 0.07f                    // LAMBDA_ROF * TAU
#define F_THETA 0.5f
#define F_INV_DENOM (1.0f / 1.07f)

// Scratch (__device__ globals; allocation-free rule)
__device__ float   g_x[3][PLANE];        // rotating x_k buffers
__device__ __half2 g_y[2][PLANE];        // ping-pong dual, (y0,y1) packed per pixel
__device__ __half2 g_w[PLANE];           // (w0,w1) packed per pixel, fp16

__device__ __forceinline__ float clip1(float v) {
    return fminf(fmaxf(v, -1.0f), 1.0f);
}

// One-time (per launch) conversion of w to packed fp16.
__global__ __launch_bounds__(256) void w_convert(const float* __restrict__ w) {
    const int i = blockIdx.x * blockDim.x + threadIdx.x;
    if (i < PLANE) g_w[i] = __floats2half2_rn(w[i], w[i + PLANE]);
}

// One fused primal-dual iteration, streaming (no smem tiling).
// x_tilde is never materialized: xt = xp + theta*(xp - xpp) recomputed at the
// 5 stencil points from the two previous x buffers (cache hits off-center).
// Divergence neighbors' y_new recomputed as in R1 (bitwise-identical fp32).
__global__ __launch_bounds__(256) void pd_iter(
    int first, int last, int xp_b, int xpp_b, int xo_b, int yin_b, int yout_b,
    const float* __restrict__ img,
    const float* __restrict__ y0f,
    float* __restrict__ dout)
{
    const int j = blockIdx.x * blockDim.x + threadIdx.x;
    const int i = blockIdx.y;
    const int idx = i * NN + j;

    const float* __restrict__ xp  = first ? img : g_x[xp_b];
    const float* __restrict__ xpp = first ? img : g_x[xpp_b];
    const __half2* __restrict__ yin = g_y[yin_b];

    // x_tilde on the fly
    #define XT(k) (xp[k] + F_THETA * (xp[k] - xpp[k]))

    const float xt_c = XT(idx);

    const __half2 wc = g_w[idx];
    const float w0c = __low2float(wc);
    const float w1c = __high2float(wc);

    float y0old, y1old;
    if (first) {
        y0old = y0f[idx];
        y1old = y0f[idx + PLANE];
    } else {
        const __half2 yc = yin[idx];
        y0old = __low2float(yc);
        y1old = __high2float(yc);
    }

    // Dual update at (i,j)
    const float gx = (j < NN - 1) ? (XT(idx + 1)  - xt_c) : 0.0f;
    const float gy = (i < MM - 1) ? (XT(idx + NN) - xt_c) : 0.0f;
    const float y0n = clip1(y0old + F_SIGMA * w0c * gx);
    const float y1n = clip1(y1old + F_SIGMA * w1c * gy);
    if (!last) g_y[yout_b][idx] = __floats2half2_rn(y0n, y1n);

    const float h_c = w0c * y0n;
    const float v_c = w1c * y1n;

    // Horizontal backward divergence
    float dh;
    if (j == 0) {
        dh = h_c;
    } else {
        const float w0l = __low2float(g_w[idx - 1]);
        float y0old_l;
        if (first) y0old_l = y0f[idx - 1];
        else       y0old_l = __low2float(yin[idx - 1]);
        const float y0l = clip1(y0old_l + F_SIGMA * w0l * (xt_c - XT(idx - 1)));
        const float h_l = w0l * y0l;
        dh = (j == NN - 1) ? -h_l : (h_c - h_l);
    }

    // Vertical backward divergence
    float dv;
    if (i == 0) {
        dv = v_c;
    } else {
        const float w1u = __high2float(g_w[idx - NN]);
        float y1old_u;
        if (first) y1old_u = y0f[idx - NN + PLANE];
        else       y1old_u = __high2float(yin[idx - NN]);
        const float y1u = clip1(y1old_u + F_SIGMA * w1u * (xt_c - XT(idx - NN)));
        const float v_u = w1u * y1u;
        dv = (i == MM - 1) ? -v_u : (v_c - v_u);
    }

    // Primal update (+ over-relaxation on the last iteration only)
    const float xo = xp[idx];
    const float xn = (xo + F_TAU * (dh + dv) + F_LT * img[idx]) * F_INV_DENOM;
    if (!last) g_x[xo_b][idx] = xn;
    else       dout[idx] = xn + F_THETA * (xn - xo);
    #undef XT
}

extern "C" void kernel_launch(void* const* d_in, const int* in_sizes, int n_in,
                              void* d_out, int out_size) {
    const float* img = (const float*)d_in[0];   // [1, 4096, 4096]
    const float* w   = (const float*)d_in[1];   // [2, 4096, 4096]
    const float* y0  = (const float*)d_in[2];   // [2, 4096, 4096]
    float* out = (float*)d_out;

    w_convert<<<PLANE / 256, 256>>>(w);

    dim3 block(256, 1, 1);
    dim3 grid(NN / 256, MM, 1);

    // Iteration k (1-based): writes x into buffer k%3, reads k-1 and k-2.
    for (int k = 1; k <= MAX_IT; ++k) {
        const int first = (k == 1);
        const int last  = (k == MAX_IT);
        const int xo_b  = k % 3;
        const int xp_b  = (k + 2) % 3;   // k-1
        const int xpp_b = (k + 1) % 3;   // k-2
        const int yin_b  = k & 1;
        const int yout_b = (k + 1) & 1;
        pd_iter<<<grid, block>>>(first, last, xp_b, xpp_b, xo_b,
                                 yin_b, yout_b, img, y0, out);
    }
}

// round 10
// speedup vs baseline: 2.2586x; 1.2639x over previous
#include <cuda_runtime.h>
#include <cuda_fp16.h>

#define MM 4096
#define NN 4096
#define PLANE (MM * NN)
#define MAX_IT 20
#define F_SIGMA 14.285714285714285f   // 1/(7*0.01)
#define F_TAU 0.01f
#define F_LT 0.07f                    // LAMBDA_ROF * TAU
#define F_THETA 0.5f
#define F_INV_DENOM (1.0f / 1.07f)

#define BX 128        // threads per block; each thread does 4 pixels

// Scratch (__device__ globals; allocation-free rule)
__device__ float   g_x[3][PLANE];        // rotating x_k buffers
__device__ __half2 g_y[2][PLANE];        // ping-pong dual, (y0,y1) packed per pixel
__device__ __half2 g_w[PLANE];           // (w0,w1) packed per pixel, fp16

__device__ __forceinline__ float clip1(float v) {
    return fminf(fmaxf(v, -1.0f), 1.0f);
}
__device__ __forceinline__ float XT(float a, float b) {
    return a + F_THETA * (a - b);
}

// One-time conversion of w to packed fp16, 4 pixels/thread.
__global__ __launch_bounds__(256) void w_convert(const float* __restrict__ w) {
    const int idx = (blockIdx.x * blockDim.x + threadIdx.x) * 4;
    const float4 a = *reinterpret_cast<const float4*>(w + idx);
    const float4 b = *reinterpret_cast<const float4*>(w + PLANE + idx);
    __half2 pk[4];
    pk[0] = __floats2half2_rn(a.x, b.x);
    pk[1] = __floats2half2_rn(a.y, b.y);
    pk[2] = __floats2half2_rn(a.z, b.z);
    pk[3] = __floats2half2_rn(a.w, b.w);
    *reinterpret_cast<uint4*>(g_w + idx) = *reinterpret_cast<uint4*>(pk);
}

// One fused primal-dual iteration, streaming, 4 px/thread, vectorized.
// Numerics identical to the R5 kernel (rel_err 5.44e-4).
__global__ __launch_bounds__(BX) void pd_iter(
    int first, int last, int xp_b, int xpp_b, int xo_b, int yin_b, int yout_b,
    const float* __restrict__ img,
    const float* __restrict__ y0f,
    float* __restrict__ dout)
{
    const int j0  = (blockIdx.x * BX + threadIdx.x) * 4;
    const int i   = blockIdx.y;
    const int idx = i * NN + j0;

    const float* __restrict__ xp  = first ? img : g_x[xp_b];
    const float* __restrict__ xpp = first ? img : g_x[xpp_b];
    const __half2* __restrict__ yin = g_y[yin_b];

    const bool has_up = (i > 0);
    const bool has_dn = (i < MM - 1);
    const bool has_l  = (j0 > 0);
    const bool has_r  = (j0 + 4 < NN);

    // ---- batched wide loads ----
    float xpv[4], xppv[4], imv[4];
    *reinterpret_cast<float4*>(xpv)  = *reinterpret_cast<const float4*>(xp  + idx);
    *reinterpret_cast<float4*>(xppv) = *reinterpret_cast<const float4*>(xpp + idx);
    *reinterpret_cast<float4*>(imv)  = *reinterpret_cast<const float4*>(img + idx);

    float xt_[6];                         // cols j0-1 .. j0+4
    xt_[1] = XT(xpv[0], xppv[0]);
    xt_[2] = XT(xpv[1], xppv[1]);
    xt_[3] = XT(xpv[2], xppv[2]);
    xt_[4] = XT(xpv[3], xppv[3]);
    xt_[0] = has_l ? XT(xp[idx - 1], xpp[idx - 1]) : 0.0f;
    xt_[5] = has_r ? XT(xp[idx + 4], xpp[idx + 4]) : 0.0f;

    float xtu[4] = {0, 0, 0, 0}, xtd[4] = {0, 0, 0, 0};
    if (has_up) {
        float a[4], b[4];
        *reinterpret_cast<float4*>(a) = *reinterpret_cast<const float4*>(xp  + idx - NN);
        *reinterpret_cast<float4*>(b) = *reinterpret_cast<const float4*>(xpp + idx - NN);
        #pragma unroll
        for (int p = 0; p < 4; ++p) xtu[p] = XT(a[p], b[p]);
    }
    if (has_dn) {
        float a[4], b[4];
        *reinterpret_cast<float4*>(a) = *reinterpret_cast<const float4*>(xp  + idx + NN);
        *reinterpret_cast<float4*>(b) = *reinterpret_cast<const float4*>(xpp + idx + NN);
        #pragma unroll
        for (int p = 0; p < 4; ++p) xtd[p] = XT(a[p], b[p]);
    }

    // w: packed (w0,w1) fp16
    float w0v[4], w1v[4], w1u[4] = {0, 0, 0, 0};
    {
        __half2 hc[4];
        *reinterpret_cast<uint4*>(hc) = *reinterpret_cast<const uint4*>(g_w + idx);
        #pragma unroll
        for (int p = 0; p < 4; ++p) { w0v[p] = __low2float(hc[p]); w1v[p] = __high2float(hc[p]); }
    }
    const float w0l = has_l ? __low2float(g_w[idx - 1]) : 0.0f;
    if (has_up) {
        __half2 hu[4];
        *reinterpret_cast<uint4*>(hu) = *reinterpret_cast<const uint4*>(g_w + idx - NN);
        #pragma unroll
        for (int p = 0; p < 4; ++p) w1u[p] = __high2float(hu[p]);
    }

    // y old
    float y0o[4], y1o[4], y1ou[4] = {0, 0, 0, 0};
    float y0ol = 0.0f;
    if (first) {
        float a[4], b[4];
        *reinterpret_cast<float4*>(a) = *reinterpret_cast<const float4*>(y0f + idx);
        *reinterpret_cast<float4*>(b) = *reinterpret_cast<const float4*>(y0f + PLANE + idx);
        #pragma unroll
        for (int p = 0; p < 4; ++p) { y0o[p] = a[p]; y1o[p] = b[p]; }
        y0ol = has_l ? y0f[idx - 1] : 0.0f;
        if (has_up) {
            float c[4];
            *reinterpret_cast<float4*>(c) = *reinterpret_cast<const float4*>(y0f + PLANE + idx - NN);
            #pragma unroll
            for (int p = 0; p < 4; ++p) y1ou[p] = c[p];
        }
    } else {
        __half2 yc[4];
        *reinterpret_cast<uint4*>(yc) = *reinterpret_cast<const uint4*>(yin + idx);
        #pragma unroll
        for (int p = 0; p < 4; ++p) { y0o[p] = __low2float(yc[p]); y1o[p] = __high2float(yc[p]); }
        y0ol = has_l ? __low2float(yin[idx - 1]) : 0.0f;
        if (has_up) {
            __half2 yu[4];
            *reinterpret_cast<uint4*>(yu) = *reinterpret_cast<const uint4*>(yin + idx - NN);
            #pragma unroll
            for (int p = 0; p < 4; ++p) y1ou[p] = __high2float(yu[p]);
        }
    }

    // ---- dual update (4 px) ----
    float y0n[4], y1n[4], h[4], v[4];
    #pragma unroll
    for (int p = 0; p < 4; ++p) {
        const bool rt = (p < 3) || has_r;                // j < NN-1
        const float gx = rt ? (xt_[p + 2] - xt_[p + 1]) : 0.0f;
        const float gy = has_dn ? (xtd[p] - xt_[p + 1]) : 0.0f;
        y0n[p] = clip1(y0o[p] + F_SIGMA * w0v[p] * gx);
        y1n[p] = clip1(y1o[p] + F_SIGMA * w1v[p] * gy);
        h[p] = w0v[p] * y0n[p];
        v[p] = w1v[p] * y1n[p];
    }
    if (!last) {
        __half2 pk[4];
        #pragma unroll
        for (int p = 0; p < 4; ++p) pk[p] = __floats2half2_rn(y0n[p], y1n[p]);
        *reinterpret_cast<uint4*>(g_y[yout_b] + idx) = *reinterpret_cast<uint4*>(pk);
    }

    // left-edge h recompute (only needed at p==0)
    float h_im1 = 0.0f;
    if (has_l) {
        const float y0l = clip1(y0ol + F_SIGMA * w0l * (xt_[1] - xt_[0]));
        h_im1 = w0l * y0l;
    }

    // ---- primal update + relax (4 px) ----
    float xnv[4];
    #pragma unroll
    for (int p = 0; p < 4; ++p) {
        const int j = j0 + p;
        const float hl = (p == 0) ? h_im1 : h[p - 1];
        float dh;
        if (j == 0)            dh = h[0];
        else if (j == NN - 1)  dh = -hl;
        else                   dh = h[p] - hl;

        float dv;
        if (!has_up) {
            dv = v[p];
        } else {
            const float y1u = clip1(y1ou[p] + F_SIGMA * w1u[p] * (xt_[p + 1] - xtu[p]));
            const float v_u = w1u[p] * y1u;
            dv = has_dn ? (v[p] - v_u) : -v_u;
        }

        const float xo = xpv[p];
        const float xn = (xo + F_TAU * (dh + dv) + F_LT * imv[p]) * F_INV_DENOM;
        xnv[p] = last ? (xn + F_THETA * (xn - xo)) : xn;
    }

    float* __restrict__ outp = last ? dout : g_x[xo_b];
    *reinterpret_cast<float4*>(outp + idx) = *reinterpret_cast<float4*>(xnv);
}

extern "C" void kernel_launch(void* const* d_in, const int* in_sizes, int n_in,
                              void* d_out, int out_size) {
    const float* img = (const float*)d_in[0];   // [1, 4096, 4096]
    const float* w   = (const float*)d_in[1];   // [2, 4096, 4096]
    const float* y0  = (const float*)d_in[2];   // [2, 4096, 4096]
    float* out = (float*)d_out;

    w_convert<<<PLANE / (4 * 256), 256>>>(w);

    dim3 block(BX, 1, 1);
    dim3 grid(NN / (4 * BX), MM, 1);

    // Iteration k (1-based): writes x into buffer k%3, reads k-1 and k-2.
    for (int k = 1; k <= MAX_IT; ++k) {
        const int first = (k == 1);
        const int last  = (k == MAX_IT);
        const int xo_b  = k % 3;
        const int xp_b  = (k + 2) % 3;   // k-1
        const int xpp_b = (k + 1) % 3;   // k-2
        const int yin_b  = k & 1;
        const int yout_b = (k + 1) & 1;
        pd_iter<<<grid, block>>>(first, last, xp_b, xpp_b, xo_b,
                                 yin_b, yout_b, img, y0, out);
    }
}

// round 12
// speedup vs baseline: 2.5220x; 1.1166x over previous
#include <cuda_runtime.h>
#include <cuda_fp16.h>

#define MM 4096
#define NN 4096
#define PLANE (MM * NN)
#define MAX_IT 20
#define F_SIGMA 14.285714285714285f   // 1/(7*0.01)
#define F_TAU 0.01f
#define F_LT 0.07f                    // LAMBDA_ROF * TAU
#define F_THETA 0.5f
#define F_INV_DENOM (1.0f / 1.07f)

#define BX 128        // threads per block; each thread does 4 pixels

// Scratch (__device__ globals; allocation-free rule)
__device__ float   g_x[3][PLANE];        // rotating x_k buffers
__device__ __half2 g_y[2][PLANE];        // ping-pong dual, (y0,y1) packed per pixel
__device__ __half2 g_w[PLANE];           // (w0,w1) packed per pixel, fp16

__device__ __forceinline__ float clip1(float v) {
    return fminf(fmaxf(v, -1.0f), 1.0f);
}
__device__ __forceinline__ float XT(float a, float b) {
    return a + F_THETA * (a - b);
}

// One-time conversion of w to packed fp16, 4 pixels/thread.
__global__ __launch_bounds__(256) void w_convert(const float* __restrict__ w) {
    const int idx = (blockIdx.x * blockDim.x + threadIdx.x) * 4;
    const float4 a = *reinterpret_cast<const float4*>(w + idx);
    const float4 b = *reinterpret_cast<const float4*>(w + PLANE + idx);
    __half2 pk[4];
    pk[0] = __floats2half2_rn(a.x, b.x);
    pk[1] = __floats2half2_rn(a.y, b.y);
    pk[2] = __floats2half2_rn(a.z, b.z);
    pk[3] = __floats2half2_rn(a.w, b.w);
    *reinterpret_cast<uint4*>(g_w + idx) = *reinterpret_cast<uint4*>(pk);
}

// One fused primal-dual iteration, streaming, 4 px/thread, vectorized.
// Template-specialized so the steady-state kernel carries no first/last
// register baggage. Numerics identical to the R8 kernel (rel_err 5.444e-4).
//  FIRST: x0 = xt0 = img (XT(img,img)==img bitwise), y from fp32 y0f.
//  LAST : no y store; writes over-relaxed x_tilde to dout.
template<bool FIRST, bool LAST>
__global__ __launch_bounds__(BX, 10) void pd_iter(
    int xp_b, int xpp_b, int xo_b, int yin_b, int yout_b,
    const float* __restrict__ img,
    const float* __restrict__ y0f,
    float* __restrict__ dout)
{
    const int j0  = (blockIdx.x * BX + threadIdx.x) * 4;
    const int i   = blockIdx.y;
    const int idx = i * NN + j0;

    const bool has_up = (i > 0);
    const bool has_dn = (i < MM - 1);
    const bool has_l  = (j0 > 0);
    const bool has_r  = (j0 + 4 < NN);

    // ---- x_tilde at stencil positions + x center + img center ----
    float imv[4], xpv[4];
    float xt_[6];                         // cols j0-1 .. j0+4
    float xtu[4] = {0, 0, 0, 0}, xtd[4] = {0, 0, 0, 0};

    *reinterpret_cast<float4*>(imv) = *reinterpret_cast<const float4*>(img + idx);

    if constexpr (FIRST) {
        #pragma unroll
        for (int p = 0; p < 4; ++p) { xpv[p] = imv[p]; xt_[p + 1] = imv[p]; }
        xt_[0] = has_l ? img[idx - 1] : 0.0f;
        xt_[5] = has_r ? img[idx + 4] : 0.0f;
        if (has_up)
            *reinterpret_cast<float4*>(xtu) = *reinterpret_cast<const float4*>(img + idx - NN);
        if (has_dn)
            *reinterpret_cast<float4*>(xtd) = *reinterpret_cast<const float4*>(img + idx + NN);
    } else {
        const float* __restrict__ xp  = g_x[xp_b];
        const float* __restrict__ xpp = g_x[xpp_b];
        float xppv[4];
        *reinterpret_cast<float4*>(xpv)  = *reinterpret_cast<const float4*>(xp  + idx);
        *reinterpret_cast<float4*>(xppv) = *reinterpret_cast<const float4*>(xpp + idx);
        #pragma unroll
        for (int p = 0; p < 4; ++p) xt_[p + 1] = XT(xpv[p], xppv[p]);
        xt_[0] = has_l ? XT(xp[idx - 1], xpp[idx - 1]) : 0.0f;
        xt_[5] = has_r ? XT(xp[idx + 4], xpp[idx + 4]) : 0.0f;
        if (has_up) {
            float a[4], b[4];
            *reinterpret_cast<float4*>(a) = *reinterpret_cast<const float4*>(xp  + idx - NN);
            *reinterpret_cast<float4*>(b) = *reinterpret_cast<const float4*>(xpp + idx - NN);
            #pragma unroll
            for (int p = 0; p < 4; ++p) xtu[p] = XT(a[p], b[p]);
        }
        if (has_dn) {
            float a[4], b[4];
            *reinterpret_cast<float4*>(a) = *reinterpret_cast<const float4*>(xp  + idx + NN);
            *reinterpret_cast<float4*>(b) = *reinterpret_cast<const float4*>(xpp + idx + NN);
            #pragma unroll
            for (int p = 0; p < 4; ++p) xtd[p] = XT(a[p], b[p]);
        }
    }

    // ---- w: packed (w0,w1) fp16 ----
    float w0v[4], w1v[4], w1u[4] = {0, 0, 0, 0};
    {
        __half2 hc[4];
        *reinterpret_cast<uint4*>(hc) = *reinterpret_cast<const uint4*>(g_w + idx);
        #pragma unroll
        for (int p = 0; p < 4; ++p) { w0v[p] = __low2float(hc[p]); w1v[p] = __high2float(hc[p]); }
    }
    const float w0l = has_l ? __low2float(g_w[idx - 1]) : 0.0f;
    if (has_up) {
        __half2 hu[4];
        *reinterpret_cast<uint4*>(hu) = *reinterpret_cast<const uint4*>(g_w + idx - NN);
        #pragma unroll
        for (int p = 0; p < 4; ++p) w1u[p] = __high2float(hu[p]);
    }

    // ---- y old ----
    float y0o[4], y1o[4], y1ou[4] = {0, 0, 0, 0};
    float y0ol = 0.0f;
    if constexpr (FIRST) {
        float a[4], b[4];
        *reinterpret_cast<float4*>(a) = *reinterpret_cast<const float4*>(y0f + idx);
        *reinterpret_cast<float4*>(b) = *reinterpret_cast<const float4*>(y0f + PLANE + idx);
        #pragma unroll
        for (int p = 0; p < 4; ++p) { y0o[p] = a[p]; y1o[p] = b[p]; }
        y0ol = has_l ? y0f[idx - 1] : 0.0f;
        if (has_up) {
            float c[4];
            *reinterpret_cast<float4*>(c) = *reinterpret_cast<const float4*>(y0f + PLANE + idx - NN);
            #pragma unroll
            for (int p = 0; p < 4; ++p) y1ou[p] = c[p];
        }
    } else {
        const __half2* __restrict__ yin = g_y[yin_b];
        __half2 yc[4];
        *reinterpret_cast<uint4*>(yc) = *reinterpret_cast<const uint4*>(yin + idx);
        #pragma unroll
        for (int p = 0; p < 4; ++p) { y0o[p] = __low2float(yc[p]); y1o[p] = __high2float(yc[p]); }
        y0ol = has_l ? __low2float(yin[idx - 1]) : 0.0f;
        if (has_up) {
            __half2 yu[4];
            *reinterpret_cast<uint4*>(yu) = *reinterpret_cast<const uint4*>(yin + idx - NN);
            #pragma unroll
            for (int p = 0; p < 4; ++p) y1ou[p] = __high2float(yu[p]);
        }
    }

    // ---- dual update (4 px) ----
    float y0n[4], y1n[4], h[4], v[4];
    #pragma unroll
    for (int p = 0; p < 4; ++p) {
        const bool rt = (p < 3) || has_r;                // j < NN-1
        const float gx = rt ? (xt_[p + 2] - xt_[p + 1]) : 0.0f;
        const float gy = has_dn ? (xtd[p] - xt_[p + 1]) : 0.0f;
        y0n[p] = clip1(y0o[p] + F_SIGMA * w0v[p] * gx);
        y1n[p] = clip1(y1o[p] + F_SIGMA * w1v[p] * gy);
        h[p] = w0v[p] * y0n[p];
        v[p] = w1v[p] * y1n[p];
    }
    if constexpr (!LAST) {
        __half2 pk[4];
        #pragma unroll
        for (int p = 0; p < 4; ++p) pk[p] = __floats2half2_rn(y0n[p], y1n[p]);
        *reinterpret_cast<uint4*>(g_y[yout_b] + idx) = *reinterpret_cast<uint4*>(pk);
    }

    // left-edge h recompute (only needed at p==0)
    float h_im1 = 0.0f;
    if (has_l) {
        const float y0l = clip1(y0ol + F_SIGMA * w0l * (xt_[1] - xt_[0]));
        h_im1 = w0l * y0l;
    }

    // ---- primal update + relax (4 px) ----
    float xnv[4];
    #pragma unroll
    for (int p = 0; p < 4; ++p) {
        const int j = j0 + p;
        const float hl = (p == 0) ? h_im1 : h[p - 1];
        float dh;
        if (j == 0)            dh = h[0];
        else if (j == NN - 1)  dh = -hl;
        else                   dh = h[p] - hl;

        float dv;
        if (!has_up) {
            dv = v[p];
        } else {
            const float y1u = clip1(y1ou[p] + F_SIGMA * w1u[p] * (xt_[p + 1] - xtu[p]));
            const float v_u = w1u[p] * y1u;
            dv = has_dn ? (v[p] - v_u) : -v_u;
        }

        const float xo = xpv[p];
        const float xn = (xo + F_TAU * (dh + dv) + F_LT * imv[p]) * F_INV_DENOM;
        xnv[p] = LAST ? (xn + F_THETA * (xn - xo)) : xn;
    }

    float* __restrict__ outp = LAST ? dout : g_x[xo_b];
    *reinterpret_cast<float4*>(outp + idx) = *reinterpret_cast<float4*>(xnv);
}

extern "C" void kernel_launch(void* const* d_in, const int* in_sizes, int n_in,
                              void* d_out, int out_size) {
    const float* img = (const float*)d_in[0];   // [1, 4096, 4096]
    const float* w   = (const float*)d_in[1];   // [2, 4096, 4096]
    const float* y0  = (const float*)d_in[2];   // [2, 4096, 4096]
    float* out = (float*)d_out;

    w_convert<<<PLANE / (4 * 256), 256>>>(w);

    dim3 block(BX, 1, 1);
    dim3 grid(NN / (4 * BX), MM, 1);

    // Iteration k (1-based): writes x into buffer k%3, reads k-1 and k-2.
    for (int k = 1; k <= MAX_IT; ++k) {
        const int xo_b  = k % 3;
        const int xp_b  = (k + 2) % 3;   // k-1
        const int xpp_b = (k + 1) % 3;   // k-2
        const int yin_b  = k & 1;
        const int yout_b = (k + 1) & 1;
        if (k == 1)
            pd_iter<true, false><<<grid, block>>>(xp_b, xpp_b, xo_b, yin_b, yout_b, img, y0, out);
        else if (k == MAX_IT)
            pd_iter<false, true><<<grid, block>>>(xp_b, xpp_b, xo_b, yin_b, yout_b, img, y0, out);
        else
            pd_iter<false, false><<<grid, block>>>(xp_b, xpp_b, xo_b, yin_b, yout_b, img, y0, out);
    }
}

// round 14
// speedup vs baseline: 3.1186x; 1.2366x over previous
#include <cuda_runtime.h>
#include <cuda_fp16.h>

#define MM 4096
#define NN 4096
#define PLANE (MM * NN)
#define MAX_IT 20
#define F_SIGMA 14.285714285714285f   // 1/(7*0.01)
#define F_TAU 0.01f
#define F_LT 0.07f                    // LAMBDA_ROF * TAU
#define F_THETA 0.5f
#define F_INV_DENOM (1.0f / 1.07f)

#define NT 544          // threads per block (>= WID)
#define WID 516         // strip width incl. 2+2 halo cols (core 512)

// Scratch (__device__ globals; allocation-free rule)
__device__ float   g_x[2][2][PLANE];   // [pair][0]=x_odd, [pair][1]=x_even
__device__ __half2 g_y[2][PLANE];      // ping-pong dual, (y0,y1) packed
__device__ __half2 g_w[PLANE];         // (w0,w1) packed fp16

__device__ __forceinline__ float clip1(float v) {
    return fminf(fmaxf(v, -1.0f), 1.0f);
}
__device__ __forceinline__ float XT(float a, float b) {
    return a + F_THETA * (a - b);
}

// One-time conversion of w to packed fp16, 4 pixels/thread.
__global__ __launch_bounds__(256) void w_convert(const float* __restrict__ w) {
    const int idx = (blockIdx.x * blockDim.x + threadIdx.x) * 4;
    const float4 a = *reinterpret_cast<const float4*>(w + idx);
    const float4 b = *reinterpret_cast<const float4*>(w + PLANE + idx);
    __half2 pk[4];
    pk[0] = __floats2half2_rn(a.x, b.x);
    pk[1] = __floats2half2_rn(a.y, b.y);
    pk[2] = __floats2half2_rn(a.z, b.z);
    pk[3] = __floats2half2_rn(a.w, b.w);
    *reinterpret_cast<uint4*>(g_w + idx) = *reinterpret_cast<uint4*>(pk);
}

// TWO fused primal-dual iterations per kernel launch, row-streaming skewed
// pipeline. Block = 512-col strip (+2 halo each side) x RS rows. Per step s:
//   A: xt row s -> smem ring          B: y1 row s-1 (h1 -> smem, v1/y1 -> regs)
//   C: x1/xt1 row s-1 (xt1 -> smem)   D: y2 row s-2 (h2 -> smem, v2 -> regs)
//   E: x2 row s-2 -> gmem
// Vertical state (v1,v2,y1,x1,img,w,xA per column) carried in registers —
// same thread owns the same column every step. fp32 interior; y crosses
// kernels as fp16 (every 2nd iter only — fewer roundings than before).
template<bool FIRST, bool LAST>
__global__ __launch_bounds__(NT, 2) void pd_fused2(
    int pair, int yin_b, int yout_b,
    const float* __restrict__ img,
    const float* __restrict__ y0f,
    float* __restrict__ dout)
{
    __shared__ float s_xt [2][WID + 4];
    __shared__ float s_xt1[2][WID + 4];
    __shared__ float s_h1[WID + 4];
    __shared__ float s_h2[WID + 4];

    const int lc = threadIdx.x;
    const int J0 = blockIdx.x * 512;
    const int b  = blockIdx.y;                  // 0..73
    const int R0 = b * 55 + min(b, 26);
    const int RS = 55 + (b < 26 ? 1 : 0);
    const int R1 = R0 + RS;

    const int j = J0 - 2 + lc;
    const bool act = (lc < WID);
    const bool jok = act && (j >= 0) && (j < NN);

    const float* __restrict__ xA = FIRST ? img : g_x[pair ^ 1][1];
    const float* __restrict__ xB = FIRST ? img : g_x[pair ^ 1][0];
    const __half2* __restrict__ yin = g_y[yin_b];
    float*   __restrict__ x1out = g_x[pair][0];
    float*   __restrict__ x2out = g_x[pair][1];
    __half2* __restrict__ yout  = g_y[yout_b];

    const int y1_lo = max(R0 - 2, 0), y1_hi = min(R1, MM - 1);
    const int x1_lo = max(R0 - 1, 0), x1_hi = min(R1, MM - 1);
    const int y2_lo = x1_lo,          y2_hi = min(R1 - 1, MM - 1);
    const int s0 = max(R0 - 2, 0), s_end = R1 + 1;

    // per-column register state (vertical carries)
    float xAp = 0.f, imp = 0.f, x1p = 0.f, v1p = 0.f, v2p = 0.f;
    float y1p0 = 0.f, y1p1 = 0.f;
    __half2 wp = __floats2half2_rn(0.f, 0.f);

    // prefetched inputs for the current step
    float nxA = 0.f, nxB = 0.f, nim = 0.f, ny0 = 0.f, ny1 = 0.f;
    __half2 nyh = wp, nw = wp;
    {
        if (jok && s0 <= MM - 1) {
            nxA = xA[s0 * NN + j];
            if (!FIRST) nxB = xB[s0 * NN + j];
        }
        const int rp = s0 - 1;
        if (jok && rp >= 0) {
            nw = g_w[rp * NN + j];
            if (FIRST) { ny0 = y0f[rp * NN + j]; ny1 = y0f[PLANE + rp * NN + j]; }
            else {
                nyh = yin[rp * NN + j];
                nim = img[rp * NN + j];
            }
        }
    }

    for (int s = s0; s <= s_end; ++s) {
        // ---- phase A: xt row s into smem ring
        if (act) {
            const float xts = FIRST ? nxA : XT(nxA, nxB);
            s_xt[s & 1][lc] = (jok && s <= MM - 1) ? xts : 0.f;
        }
        // issue prefetch for step s+1 (in flight across this step's barriers)
        float pxA = 0.f, pxB = 0.f, pim = 0.f, py0 = 0.f, py1 = 0.f;
        __half2 pyh = __floats2half2_rn(0.f, 0.f), pw = pyh;
        {
            const int sn = s + 1;
            if (jok && sn <= s_end && sn <= MM - 1) {
                pxA = xA[sn * NN + j];
                if (!FIRST) pxB = xB[sn * NN + j];
            }
            if (jok && s >= 0 && s <= y1_hi) {
                pw = g_w[s * NN + j];
                if (FIRST) { py0 = y0f[s * NN + j]; py1 = y0f[PLANE + s * NN + j]; }
                else {
                    pyh = yin[s * NN + j];
                    pim = img[s * NN + j];
                }
            }
        }
        __syncthreads();

        // ---- phase B: dual iter-1, row s-1
        const int r1 = s - 1;
        float v1c = 0.f, y1c0 = 0.f, y1c1 = 0.f;
        if (jok && lc < WID - 1 && r1 >= y1_lo && r1 <= y1_hi) {
            const float xtc = s_xt[(s - 1) & 1][lc];
            const float gx = (j < NN - 1) ? s_xt[(s - 1) & 1][lc + 1] - xtc : 0.f;
            const float gy = (r1 < MM - 1) ? s_xt[s & 1][lc] - xtc : 0.f;
            const float w0 = __low2float(nw), w1 = __high2float(nw);
            float yo0, yo1;
            if (FIRST) { yo0 = ny0; yo1 = ny1; }
            else { yo0 = __low2float(nyh); yo1 = __high2float(nyh); }
            y1c0 = clip1(yo0 + F_SIGMA * w0 * gx);
            y1c1 = clip1(yo1 + F_SIGMA * w1 * gy);
            s_h1[lc] = w0 * y1c0;
            v1c = w1 * y1c1;
        }
        __syncthreads();

        // ---- phase C: primal + relax iter-1, row s-1
        float x1c = 0.f;
        if (jok && lc >= 1 && lc < WID - 1 && r1 >= x1_lo && r1 <= x1_hi) {
            const float h_c = s_h1[lc];
            float dh;
            if (j == 0) dh = h_c;
            else { const float h_l = s_h1[lc - 1]; dh = (j == NN - 1) ? -h_l : h_c - h_l; }
            float dv;
            if (r1 == 0) dv = v1c;
            else dv = (r1 == MM - 1) ? -v1p : v1c - v1p;
            const float imv = FIRST ? xAp : nim;        // img[s-1]
            x1c = (xAp + F_TAU * (dh + dv) + F_LT * imv) * F_INV_DENOM;
            s_xt1[r1 & 1][lc] = x1c + F_THETA * (x1c - xAp);
            if (!LAST && lc >= 2 && lc < WID - 2 && r1 >= R0 && r1 < R1)
                x1out[r1 * NN + j] = x1c;
        }
        __syncthreads();

        // ---- phase D: dual iter-2, row s-2
        const int r2 = s - 2;
        float v2c = 0.f;
        if (jok && lc >= 1 && lc < WID - 2 && r2 >= y2_lo && r2 <= y2_hi) {
            const float xt1c = s_xt1[r2 & 1][lc];
            const float gx = (j < NN - 1) ? s_xt1[r2 & 1][lc + 1] - xt1c : 0.f;
            const float gy = (r2 < MM - 1) ? s_xt1[(r2 + 1) & 1][lc] - xt1c : 0.f;
            const float w0 = __low2float(wp), w1 = __high2float(wp);
            const float y20 = clip1(y1p0 + F_SIGMA * w0 * gx);
            const float y21 = clip1(y1p1 + F_SIGMA * w1 * gy);
            s_h2[lc] = w0 * y20;
            v2c = w1 * y21;
            if (!LAST && lc >= 2 && r2 >= R0 && r2 < R1)
                yout[r2 * NN + j] = __floats2half2_rn(y20, y21);
        }
        __syncthreads();

        // ---- phase E: primal iter-2, row s-2 (core only) -> gmem
        if (lc >= 2 && lc < WID - 2 && r2 >= R0 && r2 < R1) {
            const float h_c = s_h2[lc];
            float dh;
            if (j == 0) dh = h_c;
            else { const float h_l = s_h2[lc - 1]; dh = (j == NN - 1) ? -h_l : h_c - h_l; }
            float dv;
            if (r2 == 0) dv = v2c;
            else dv = (r2 == MM - 1) ? -v2p : v2c - v2p;
            const float x2 = (x1p + F_TAU * (dh + dv) + F_LT * imp) * F_INV_DENOM;
            if (LAST) dout[r2 * NN + j] = x2 + F_THETA * (x2 - x1p);
            else      x2out[r2 * NN + j] = x2;
        }

        // ---- shift per-column state (order matters: imp before xAp)
        v1p = v1c; v2p = v2c; x1p = x1c;
        y1p0 = y1c0; y1p1 = y1c1;
        wp = nw;
        imp = FIRST ? xAp : nim;
        xAp = nxA;
        nxA = pxA; nxB = pxB; nim = pim; nw = pw; nyh = pyh; ny0 = py0; ny1 = py1;
    }
}

extern "C" void kernel_launch(void* const* d_in, const int* in_sizes, int n_in,
                              void* d_out, int out_size) {
    const float* img = (const float*)d_in[0];   // [1, 4096, 4096]
    const float* w   = (const float*)d_in[1];   // [2, 4096, 4096]
    const float* y0  = (const float*)d_in[2];   // [2, 4096, 4096]
    float* out = (float*)d_out;

    w_convert<<<PLANE / (4 * 256), 256>>>(w);

    dim3 grid(8, 74);   // 8 col-strips x 74 row-strips = 592 blocks (2 waves)

    // Fused kernel t does iterations 2t+1, 2t+2 (t = 0..9).
    for (int t = 0; t < MAX_IT / 2; ++t) {
        const int pair   = t & 1;
        const int yout_b = t & 1;
        const int yin_b  = (t + 1) & 1;   // = (t-1)&1 for t>=1; unused for t==0
        if (t == 0)
            pd_fused2<true,  false><<<grid, NT>>>(pair, yin_b, yout_b, img, y0, out);
        else if (t == MAX_IT / 2 - 1)
            pd_fused2<false, true ><<<grid, NT>>>(pair, yin_b, yout_b, img, y0, out);
        else
            pd_fused2<false, false><<<grid, NT>>>(pair, yin_b, yout_b, img, y0, out);
    }
}